// round 16
// baseline (speedup 1.0000x reference)
#include <cuda_runtime.h>
#include <cuda_fp16.h>
#include <math.h>

#define NB 64
#define NN 4096
#define ROWS (NB*NN)          // 262144
#define SCALE 0.125f
#define LN_EPS 1e-5f
#define SUM_EPS 1e-8f

// ---------------- device scratch (no allocations allowed) ----------------
__device__ __align__(16) __half g_k16[(size_t)ROWS*256];   // [row][d] fp16 k
__device__ __align__(16) __half g_v16[(size_t)ROWS*256];   // [row][d] fp16 v
__device__ float g_WqT[256*256];
__device__ float g_WihT[256*768];
__device__ float g_WhhT[256*768];
__device__ float g_q[512*256];             // [(b*8+i)][h*64+d], pre-scaled
__device__ float g_denom[NB*32];
__device__ float g_upd[512*256];           // UNNORMALIZED sum(e*v); /denom in gru
__device__ float g_slotsA[512*256];
__device__ float g_slotsB[512*256];
// row-major fp16 image of Wk|Wv: [o in 0..511][k in 0..255]
__device__ __align__(16) unsigned short g_B_img[512*256];

// ---------------- f32x2 packed-FMA helpers (Blackwell) ----------------
#define PK2(d,x,y)   asm("mov.b64 %0, {%1,%2};"          : "=l"(d) : "f"(x), "f"(y))
#define UPK2(x,y,d)  asm("mov.b64 {%0,%1}, %2;"          : "=f"(x), "=f"(y) : "l"(d))
#define FMA2(d,a,b,c) asm("fma.rn.f32x2 %0, %1, %2, %3;" : "=l"(d) : "l"(a), "l"(b), "l"(c))

// ---------------- baseline-PTX tensor-core helpers (sm_80+) ----------------
__device__ __forceinline__ unsigned smem_u32(const void* p) {
    unsigned a;
    asm("{ .reg .u64 t; cvta.to.shared.u64 t, %1; cvt.u32.u64 %0, t; }" : "=r"(a) : "l"(p));
    return a;
}
#define LDSM4(r, a) \
    asm volatile("ldmatrix.sync.aligned.m8n8.x4.shared.b16 {%0,%1,%2,%3}, [%4];" \
        : "=r"((r)[0]), "=r"((r)[1]), "=r"((r)[2]), "=r"((r)[3]) : "r"(a))
#define MMA16816(d, a, b) \
    asm volatile("mma.sync.aligned.m16n8k16.row.col.f32.f16.f16.f32 " \
        "{%0,%1,%2,%3},{%4,%5,%6,%7},{%8,%9},{%0,%1,%2,%3};" \
        : "+f"((d)[0]), "+f"((d)[1]), "+f"((d)[2]), "+f"((d)[3]) \
        : "r"((a)[0]), "r"((a)[1]), "r"((a)[2]), "r"((a)[3]), "r"((b)[0]), "r"((b)[1]))
#define CP_ASYNC16(dst, src) \
    asm volatile("cp.async.cg.shared.global [%0], [%1], 16;" :: "r"(dst), "l"(src))
#define CP_COMMIT() asm volatile("cp.async.commit_group;" ::: "memory")
#define CP_WAIT1()  asm volatile("cp.async.wait_group 1;"  ::: "memory")
#define CP_WAIT0()  asm volatile("cp.async.wait_group 0;"  ::: "memory")

// ---------------- prep: transpose weights (Wq / GRU) ----------------
__global__ void prep_w(const float* __restrict__ Wq, const float* __restrict__ wih,
                       const float* __restrict__ whh) {
    int idx = blockIdx.x*256 + threadIdx.x;          // < 196608
    if (idx < 256*256) {
        int d = idx >> 8, o = idx & 255;
        g_WqT[idx] = Wq[o*256 + d];
    }
    {
        int d = idx / 768, o = idx - d*768;
        g_WihT[idx] = wih[o*256 + d];
        g_WhhT[idx] = whh[o*256 + d];
    }
}

// ---------------- prep: fp16 image of Wk|Wv (plain row-major) --------
__global__ void prep_b(const float* __restrict__ Wk, const float* __restrict__ Wv) {
    int o = blockIdx.x, k = threadIdx.x;
    float w = (o < 256) ? Wk[o*256 + k] : Wv[(o-256)*256 + k];
    g_B_img[o*256 + k] = __half_as_ushort(__float2half_rn(w));
}

// ---------------- HMMA K/V GEMM fragments (pure fp16) ----------
struct Frags {
    unsigned a0[4], a1[4];   // A (2 m-tiles)
    unsigned bh[8];          // B (2 n-sub-tiles)
};

__device__ __forceinline__ void load_frags(
    Frags& f, int ks, int half, unsigned buf,
    unsigned aBase0, unsigned aBase1, unsigned klA, unsigned xA,
    unsigned nB0row, unsigned nB1row, unsigned kbB, unsigned xB)
{
    unsigned kgA = (unsigned)(half*8 + ks)*2u + klA;
    unsigned aoff = ((kgA ^ xA) << 4);
    LDSM4(f.a0, aBase0 + aoff);
    LDSM4(f.a1, aBase1 + aoff);
    unsigned kgB = (unsigned)ks*2u + kbB;
    LDSM4(&f.bh[0], buf + nB0row + ((kgB ^ xB) << 4));
    LDSM4(&f.bh[4], buf + nB1row + ((kgB ^ xB) << 4));
}

__device__ __forceinline__ void do_mmas(float acc[2][4][4], const Frags& f) {
#pragma unroll
    for (int j = 0; j < 4; j++) {
        MMA16816(acc[0][j], f.a0, &f.bh[j*2]);
        MMA16816(acc[1][j], f.a1, &f.bh[j*2]);
    }
}

// ---------------- HMMA K/V GEMM: [262144,256] @ [256,512], fp16 ----
// CTA = 128 rows x 512 outputs, 2 CTAs/SM. LN stats computed inline.
// A fp16 resident; B streamed in 16 chunks of 16KB via cp.async dbl-buffer.
// Outputs written fp16 row-major to g_k16 / g_v16.
#define KV_SMEM 98304

__global__ void __launch_bounds__(256, 2)
kv_hmma(const float* __restrict__ x, const float* __restrict__ lw,
        const float* __restrict__ lb) {
    extern __shared__ char smem[];
    __shared__ float smu[128], srs[128];

    const unsigned sb  = smem_u32(smem);
    const unsigned sbB = sb + 65536u;
    int tid = threadIdx.x, wid = tid >> 5, lane = tid & 31;
    int m0 = blockIdx.x * 128;

    // ---- prefetch B chunk 0 into buffer 0 (16KB = 1024 float4) ----
    {
#pragma unroll
        for (int it = 0; it < 4; it++) {
            int u = tid + it*256;
            int o = u >> 4, g = u & 15;
            const char* src = (const char*)g_B_img + (size_t)o*512 + g*16;
            unsigned dst = sbB + o*256 + ((unsigned)(g ^ (o & 7)) << 4);
            CP_ASYNC16(dst, src);
        }
        CP_COMMIT();
    }

    // ---- inline LN stats: warp wid handles rows wid*16 .. wid*16+15 ----
#pragma unroll 2
    for (int r = 0; r < 16; r++) {
        int row = wid*16 + r;
        const float4* xr = (const float4*)(x + (size_t)(m0 + row)*256);
        float4 v0 = xr[lane*2], v1 = xr[lane*2 + 1];
        float s  = v0.x + v0.y + v0.z + v0.w + v1.x + v1.y + v1.z + v1.w;
        float ss = v0.x*v0.x + v0.y*v0.y + v0.z*v0.z + v0.w*v0.w
                 + v1.x*v1.x + v1.y*v1.y + v1.z*v1.z + v1.w*v1.w;
#pragma unroll
        for (int o = 16; o; o >>= 1) {
            s  += __shfl_xor_sync(0xffffffffu, s,  o);
            ss += __shfl_xor_sync(0xffffffffu, ss, o);
        }
        if (lane == 0) {
            float mu = s * (1.f/256.f);
            smu[row] = mu;
            srs[row] = rsqrtf(ss * (1.f/256.f) - mu*mu + LN_EPS);
        }
    }
    __syncthreads();

    // ---- load A with fused LN, fp16, swizzled ----
    {
        int cpair = tid & 127;            // column pair index
        int c2 = cpair * 2;
        int rbase = (tid >> 7) * 64;
        float w0 = lw[c2], w1 = lw[c2+1], bb0 = lb[c2], bb1 = lb[c2+1];
        unsigned gA = (unsigned)(cpair >> 2);
        unsigned boff = (unsigned)(cpair & 3) * 4u;
#pragma unroll 4
        for (int r = 0; r < 64; r++) {
            int row = rbase + r;
            float2 xv = *(const float2*)&x[(size_t)(m0 + row)*256 + c2];
            float mu = smu[row], rs = srs[row];
            float v0 = (xv.x - mu)*rs*w0 + bb0;
            float v1 = (xv.y - mu)*rs*w1 + bb1;
            unsigned hp = (unsigned)__half_as_ushort(__float2half_rn(v0)) |
                          ((unsigned)__half_as_ushort(__float2half_rn(v1)) << 16);
            unsigned phys = (unsigned)row*512u + ((gA ^ (unsigned)(row & 7)) << 4) + boff;
            *(unsigned*)(smem + phys) = hp;
        }
    }

    // ---- warp tiling: 4 M-warps x 2 N-warps, warp tile m32 x n32 ----
    int mw = wid >> 1, nw = wid & 1;
    int rA0 = mw*32 + (lane & 15);
    int rA1 = rA0 + 16;
    unsigned klA = (unsigned)(lane >> 4);
    unsigned xA = (unsigned)(rA0 & 7);
    unsigned aBase0 = sb + (unsigned)rA0*512u;
    unsigned aBase1 = sb + (unsigned)rA1*512u;

    int nB0 = nw*32 + (lane & 7) + ((lane >> 4) & 1)*8;
    int nB1 = nB0 + 16;
    unsigned nB0row = (unsigned)nB0*256u;
    unsigned nB1row = (unsigned)nB1*256u;
    unsigned kbB = (unsigned)((lane >> 3) & 1);
    unsigned xB = (unsigned)(nB0 & 7);

    float acc[2][4][4];
#pragma unroll
    for (int i = 0; i < 2; i++)
#pragma unroll
        for (int j = 0; j < 4; j++)
#pragma unroll
            for (int q = 0; q < 4; q++) acc[i][j][q] = 0.f;

    for (int c = 0; c < 16; c++) {
        if (c + 1 < 16) {
            int nbn = (c + 1) >> 1, halfn = (c + 1) & 1;
            unsigned bufn = sbB + (unsigned)((c + 1) & 1)*16384u;
#pragma unroll
            for (int it = 0; it < 4; it++) {
                int u = tid + it*256;
                int o = u >> 4, g = u & 15;
                const char* src = (const char*)g_B_img
                    + (size_t)(nbn*64 + o)*512 + halfn*256 + g*16;
                unsigned dst = bufn + o*256 + ((unsigned)(g ^ (o & 7)) << 4);
                CP_ASYNC16(dst, src);
            }
            CP_COMMIT();
            CP_WAIT1();
        } else {
            CP_WAIT0();
        }
        __syncthreads();

        unsigned buf = sbB + (unsigned)(c & 1)*16384u;
        int half = c & 1;

        Frags fr0, fr1;
        load_frags(fr0, 0, half, buf, aBase0, aBase1, klA, xA,
                   nB0row, nB1row, kbB, xB);
#pragma unroll
        for (int ks = 0; ks < 8; ks++) {
            Frags& cur = (ks & 1) ? fr1 : fr0;
            Frags& nxt = (ks & 1) ? fr0 : fr1;
            if (ks < 7)
                load_frags(nxt, ks + 1, half, buf, aBase0, aBase1, klA, xA,
                           nB0row, nB1row, kbB, xB);
            do_mmas(acc, cur);
        }

        if (c & 1) {
            int nbidx = c >> 1;
#pragma unroll
            for (int i = 0; i < 2; i++) {
#pragma unroll
                for (int j = 0; j < 4; j++) {
                    int row = m0 + mw*32 + i*16 + (lane >> 2);
                    int col = nbidx*64 + nw*32 + j*8 + (lane & 3)*2;
                    __half2 h0 = __floats2half2_rn(acc[i][j][0], acc[i][j][1]);
                    __half2 h1 = __floats2half2_rn(acc[i][j][2], acc[i][j][3]);
                    if (nbidx < 4) {
                        *(__half2*)&g_k16[(size_t)row*256 + col]       = h0;
                        *(__half2*)&g_k16[(size_t)(row + 8)*256 + col] = h1;
                    } else {
                        int vc = col - 256;
                        *(__half2*)&g_v16[(size_t)row*256 + vc]       = h0;
                        *(__half2*)&g_v16[(size_t)(row + 8)*256 + vc] = h1;
                    }
                    acc[i][j][0] = acc[i][j][1] = acc[i][j][2] = acc[i][j][3] = 0.f;
                }
            }
        }
        __syncthreads();
    }
}

// ---------------- slot LN + q projection (+ zero denom & upd) --------------
__global__ void __launch_bounds__(256)
slot_q(int it, const float* __restrict__ cond,
       const float* __restrict__ lw, const float* __restrict__ lb) {
    const float* src = (it == 0) ? cond : (it == 1 ? g_slotsA : g_slotsB);
    int b = blockIdx.x, t = threadIdx.x, wid = t >> 5, lane = t & 31;

    __shared__ float sn[8][256];
    __shared__ float wt[32][256];

    const float4* row = (const float4*)(src + (size_t)(b*8 + wid)*256);
    float4 v0 = row[lane], v1 = row[lane + 32];
    float s  = v0.x + v0.y + v0.z + v0.w + v1.x + v1.y + v1.z + v1.w;
    float ss = v0.x*v0.x + v0.y*v0.y + v0.z*v0.z + v0.w*v0.w
             + v1.x*v1.x + v1.y*v1.y + v1.z*v1.z + v1.w*v1.w;
#pragma unroll
    for (int o = 16; o; o >>= 1) {
        s  += __shfl_xor_sync(0xffffffffu, s,  o);
        ss += __shfl_xor_sync(0xffffffffu, ss, o);
    }
    float mu = s * (1.f/256.f);
    float rs = rsqrtf(ss * (1.f/256.f) - mu*mu + LN_EPS);
#pragma unroll
    for (int i = 0; i < 2; i++) {
        float4 xv = i ? v1 : v0;
        int c = (lane + 32*i) * 4;
        float4 w4 = *(const float4*)&lw[c];
        float4 b4 = *(const float4*)&lb[c];
        sn[wid][c+0] = (xv.x - mu)*rs*w4.x + b4.x;
        sn[wid][c+1] = (xv.y - mu)*rs*w4.y + b4.y;
        sn[wid][c+2] = (xv.z - mu)*rs*w4.z + b4.z;
        sn[wid][c+3] = (xv.w - mu)*rs*w4.w + b4.w;
    }
    if (t < 32) g_denom[b*32 + t] = 0.f;
#pragma unroll
    for (int i = 0; i < 8; i++) g_upd[b*2048 + i*256 + t] = 0.f;
    __syncthreads();

    float acc[8] = {0,0,0,0,0,0,0,0};
    for (int d0 = 0; d0 < 256; d0 += 32) {
        __syncthreads();
#pragma unroll
        for (int i = 0; i < 8; i++) {
            int u = t + i*256;
            int dd = u >> 6, g = u & 63;
            *(float4*)&wt[dd][g*4] = *(const float4*)&g_WqT[(d0 + dd)*256 + g*4];
        }
        __syncthreads();
#pragma unroll 4
        for (int dd = 0; dd < 32; dd++) {
            float w = wt[dd][t];
#pragma unroll
            for (int r = 0; r < 8; r++) acc[r] += sn[r][d0 + dd] * w;
        }
    }
#pragma unroll
    for (int r = 0; r < 8; r++) g_q[(size_t)(b*8 + r)*256 + t] = acc[r] * SCALE;
}

// ---------------- FUSED dots + softmax + updates -----------------------
// grid (16, 64): block handles j in [jt*256, jt*256+256) of batch b.
// Phase 1: thread-per-j dots + 32-way softmax (e kept in regs, staged fp32).
// Phase 2: same block contracts its 256 j's with v -> atomicAdd into g_upd
//          (UNNORMALIZED; divided by denom in gru).
__global__ void __launch_bounds__(256)
dots_upd(float* __restrict__ out_stack, float* __restrict__ out_last) {
    int b = blockIdx.y, jt = blockIdx.x;
    int tid = threadIdx.x, lane = tid & 31;
    int j = jt*256 + tid;

    __shared__ __align__(16) float qs2[2048];
    __shared__ float attn_s[32][257];
    __shared__ float den_s[32];

#pragma unroll
    for (int r = 0; r < 8; r++) {
        int u = r*256 + tid;
        int hd = u >> 3, p = (u >> 1) & 3, hf = u & 1;
        qs2[u] = g_q[(size_t)(b*8 + 2*p + hf)*256 + hd];
    }
    if (tid < 32) den_s[tid] = 0.f;
    __syncthreads();

    // ---- phase 1: dots ----
    unsigned long long accp[16];
#pragma unroll
    for (int i = 0; i < 16; i++) accp[i] = 0ull;

    const __half* krow = g_k16 + (size_t)(b*NN + j)*256;
#pragma unroll 4
    for (int hd0 = 0; hd0 < 256; hd0 += 8) {
        uint4 kq = *(const uint4*)(krow + hd0);
        int h = hd0 >> 6;
#pragma unroll
        for (int u = 0; u < 4; u++) {
            unsigned kk = (&kq.x)[u];
            float2 kf = __half22float2(*(const __half2*)&kk);
            int hd = hd0 + u*2;
            unsigned long long kpx, kpy;
            PK2(kpx, kf.x, kf.x);
            PK2(kpy, kf.y, kf.y);
            ulonglong2 qa = *(const ulonglong2*)&qs2[hd*8];
            ulonglong2 qb = *(const ulonglong2*)&qs2[hd*8 + 4];
            FMA2(accp[0  + h], kpx, qa.x, accp[0  + h]);
            FMA2(accp[4  + h], kpx, qa.y, accp[4  + h]);
            FMA2(accp[8  + h], kpx, qb.x, accp[8  + h]);
            FMA2(accp[12 + h], kpx, qb.y, accp[12 + h]);
            ulonglong2 qc = *(const ulonglong2*)&qs2[(hd+1)*8];
            ulonglong2 qd = *(const ulonglong2*)&qs2[(hd+1)*8 + 4];
            FMA2(accp[0  + h], kpy, qc.x, accp[0  + h]);
            FMA2(accp[4  + h], kpy, qc.y, accp[4  + h]);
            FMA2(accp[8  + h], kpy, qd.x, accp[8  + h]);
            FMA2(accp[12 + h], kpy, qd.y, accp[12 + h]);
        }
    }

    float e[32];
#pragma unroll
    for (int p = 0; p < 4; p++)
#pragma unroll
        for (int h = 0; h < 4; h++)
            UPK2(e[(2*p)*4 + h], e[(2*p+1)*4 + h], accp[p*4 + h]);

    float mx = e[0];
#pragma unroll
    for (int i = 1; i < 32; i++) mx = fmaxf(mx, e[i]);
    float ssum = 0.f;
#pragma unroll
    for (int i = 0; i < 32; i++) { e[i] = __expf(e[i] - mx); ssum += e[i]; }
    float inv = 1.f / ssum;
#pragma unroll
    for (int i = 0; i < 32; i++) e[i] *= inv;

    // stage attn fp32 for phase 2
#pragma unroll
    for (int ih = 0; ih < 32; ih++) attn_s[ih][tid] = e[ih];

    // per-ih denominators: warp-reduce then smem atomics
#pragma unroll
    for (int i = 0; i < 32; i++) {
        float v = e[i];
        v += __shfl_xor_sync(0xffffffffu, v, 1);
        v += __shfl_xor_sync(0xffffffffu, v, 2);
        v += __shfl_xor_sync(0xffffffffu, v, 4);
        v += __shfl_xor_sync(0xffffffffu, v, 8);
        v += __shfl_xor_sync(0xffffffffu, v, 16);
        if (lane == 0) atomicAdd(&den_s[i], v);
    }

    // head-mean outputs
#pragma unroll
    for (int i = 0; i < 8; i++) {
        float ms = 0.25f*(e[i*4] + e[i*4+1] + e[i*4+2] + e[i*4+3]);
        size_t o = (size_t)(b*8 + i)*NN + j;
        out_stack[o] = ms;
        if (out_last) out_last[o] = ms;
    }
    __syncthreads();
    if (tid < 32) atomicAdd(&g_denom[b*32 + tid], den_s[tid]);

    // ---- phase 2: updates (unnormalized) ----
    int grp = tid >> 7;            // j-half: 0 -> [0,128), 1 -> [128,256)
    int d2  = tid & 127;           // d pair index, d = 2*d2
    int h   = d2 >> 5;             // head of this d

    unsigned long long acc2[8];
#pragma unroll
    for (int i = 0; i < 8; i++) acc2[i] = 0ull;

    const __half* vbase = g_v16 + (size_t)(b*NN + jt*256 + grp*128)*256 + d2*2;
#pragma unroll 4
    for (int jj = 0; jj < 128; jj++) {
        __half2 vh = *(const __half2*)(vbase + (size_t)jj*256);
        float2 vf = __half22float2(vh);
        unsigned long long vp; PK2(vp, vf.x, vf.y);
        int jc = grp*128 + jj;
#pragma unroll
        for (int i = 0; i < 8; i++) {
            float at = attn_s[i*4 + h][jc];
            unsigned long long ap; PK2(ap, at, at);
            FMA2(acc2[i], vp, ap, acc2[i]);
        }
    }
#pragma unroll
    for (int i = 0; i < 8; i++) {
        float a0, a1; UPK2(a0, a1, acc2[i]);
        float* dst = &g_upd[(b*8 + i)*256 + d2*2];
        atomicAdd(dst,     a0);
        atomicAdd(dst + 1, a1);
    }
}

// ---------------- GRU cell (normalizes updates by denom) -------------------
__global__ void __launch_bounds__(256)
gru_kernel(int it, const float* __restrict__ cond, float* __restrict__ out_slots,
           const float* __restrict__ bih, const float* __restrict__ bhh) {
    const float* hsrc = (it == 0) ? cond : (it == 1 ? g_slotsA : g_slotsB);
    float* dst = (it == 0) ? g_slotsA : (it == 1 ? g_slotsB : out_slots);
    int t = threadIdx.x;
    __shared__ float u_s[4][256], h_s[4][256];
#pragma unroll
    for (int r = 0; r < 4; r++) {
        int row = blockIdx.x*4 + r;
        int bb = row >> 3, ii = row & 7;
        float dinv = 1.f / (g_denom[bb*32 + ii*4 + (t >> 6)] + SUM_EPS);
        u_s[r][t] = g_upd[row*256 + t] * dinv;
        h_s[r][t] = hsrc[row*256 + t];
    }
    __syncthreads();
    float axr[4] = {0,0,0,0}, axz[4] = {0,0,0,0}, axn[4] = {0,0,0,0};
    float ahr[4] = {0,0,0,0}, ahz[4] = {0,0,0,0}, ahn[4] = {0,0,0,0};
#pragma unroll 2
    for (int dd = 0; dd < 256; dd++) {
        float wr = g_WihT[dd*768 + t],       wz = g_WihT[dd*768 + 256 + t];
        float wn = g_WihT[dd*768 + 512 + t];
        float vr = g_WhhT[dd*768 + t],       vz = g_WhhT[dd*768 + 256 + t];
        float vn = g_WhhT[dd*768 + 512 + t];
#pragma unroll
        for (int r = 0; r < 4; r++) {
            float u = u_s[r][dd], hh = h_s[r][dd];
            axr[r] += u*wr;  axz[r] += u*wz;  axn[r] += u*wn;
            ahr[r] += hh*vr; ahz[r] += hh*vz; ahn[r] += hh*vn;
        }
    }
    float br = bih[t], bz = bih[256 + t], bn = bih[512 + t];
    float cr = bhh[t], cz = bhh[256 + t], cn = bhh[512 + t];
#pragma unroll
    for (int r = 0; r < 4; r++) {
        float rg = 1.f / (1.f + __expf(-(axr[r] + ahr[r] + br + cr)));
        float zg = 1.f / (1.f + __expf(-(axz[r] + ahz[r] + bz + cz)));
        float ng = tanhf(axn[r] + bn + rg*(ahn[r] + cn));
        int row = blockIdx.x*4 + r;
        dst[row*256 + t] = (1.f - zg)*ng + zg*h_s[r][t];
    }
}

// ---------------- launch ----------------
extern "C" void kernel_launch(void* const* d_in, const int* in_sizes, int n_in,
                              void* d_out, int out_size) {
    (void)in_sizes; (void)n_in; (void)out_size;
    const float* x    = (const float*)d_in[0];
    const float* cond = (const float*)d_in[1];
    const float* lniw = (const float*)d_in[2];
    const float* lnib = (const float*)d_in[3];
    const float* lnsw = (const float*)d_in[4];
    const float* lnsb = (const float*)d_in[5];
    const float* Wq   = (const float*)d_in[6];
    const float* Wk   = (const float*)d_in[7];
    const float* Wv   = (const float*)d_in[8];
    const float* wih  = (const float*)d_in[9];
    const float* whh  = (const float*)d_in[10];
    const float* bih  = (const float*)d_in[11];
    const float* bhh  = (const float*)d_in[12];

    float* out       = (float*)d_out;
    float* out_slots = out;                       // [64,8,256]
    float* out_last  = out + 131072;              // [64,8,4096]
    float* out_stack = out + 131072 + 2097152;    // [3,64,8,4096]

    cudaFuncSetAttribute(kv_hmma, cudaFuncAttributeMaxDynamicSharedMemorySize, KV_SMEM);

    prep_w<<<768, 256>>>(Wq, wih, whh);
    prep_b<<<512, 256>>>(Wk, Wv);
    kv_hmma<<<2048, 256, KV_SMEM>>>(x, lniw, lnib);

    for (int it = 0; it < 3; it++) {
        slot_q<<<64, 256>>>(it, cond, lnsw, lnsb);
        dots_upd<<<dim3(16, 64), 256>>>(out_stack + (size_t)it*2097152,
                                        (it == 2) ? out_last : (float*)0);
        gru_kernel<<<128, 256>>>(it, cond, out_slots, bih, bhh);
    }
}

// round 17
// speedup vs baseline: 1.2744x; 1.2744x over previous
#include <cuda_runtime.h>
#include <cuda_fp16.h>
#include <math.h>

#define NB 64
#define NN 4096
#define ROWS (NB*NN)          // 262144
#define SCALE 0.125f
#define LN_EPS 1e-5f
#define SUM_EPS 1e-8f

// ---------------- device scratch (no allocations allowed) ----------------
__device__ __align__(16) __half g_k16[(size_t)ROWS*256];   // [row][d] fp16 k
__device__ __align__(16) __half g_v16[(size_t)ROWS*256];   // [row][d] fp16 v
__device__ float g_WqT[256*256];
__device__ float g_WihT[256*768];
__device__ float g_WhhT[256*768];
__device__ float g_q[512*256];             // [(b*8+i)][h*64+d], pre-scaled
__device__ float g_denom[NB*32];
__device__ float g_upd[512*256];           // UNNORMALIZED sum(e*v); /denom in gru
__device__ float g_slotsA[512*256];
__device__ float g_slotsB[512*256];
// row-major fp16 image of Wk|Wv: [o in 0..511][k in 0..255]
__device__ __align__(16) unsigned short g_B_img[512*256];

// ---------------- packed helpers ----------------
#define PK2(d,x,y)   asm("mov.b64 %0, {%1,%2};"          : "=l"(d) : "f"(x), "f"(y))
#define UPK2(x,y,d)  asm("mov.b64 {%0,%1}, %2;"          : "=f"(x), "=f"(y) : "l"(d))

// ---------------- baseline-PTX tensor-core helpers (sm_80+) ----------------
__device__ __forceinline__ unsigned smem_u32(const void* p) {
    unsigned a;
    asm("{ .reg .u64 t; cvta.to.shared.u64 t, %1; cvt.u32.u64 %0, t; }" : "=r"(a) : "l"(p));
    return a;
}
#define LDSM4(r, a) \
    asm volatile("ldmatrix.sync.aligned.m8n8.x4.shared.b16 {%0,%1,%2,%3}, [%4];" \
        : "=r"((r)[0]), "=r"((r)[1]), "=r"((r)[2]), "=r"((r)[3]) : "r"(a))
#define LDSM4T(r, a) \
    asm volatile("ldmatrix.sync.aligned.m8n8.x4.trans.shared.b16 {%0,%1,%2,%3}, [%4];" \
        : "=r"((r)[0]), "=r"((r)[1]), "=r"((r)[2]), "=r"((r)[3]) : "r"(a))
#define MMA16816(d, a, b) \
    asm volatile("mma.sync.aligned.m16n8k16.row.col.f32.f16.f16.f32 " \
        "{%0,%1,%2,%3},{%4,%5,%6,%7},{%8,%9},{%0,%1,%2,%3};" \
        : "+f"((d)[0]), "+f"((d)[1]), "+f"((d)[2]), "+f"((d)[3]) \
        : "r"((a)[0]), "r"((a)[1]), "r"((a)[2]), "r"((a)[3]), "r"((b)[0]), "r"((b)[1]))
#define CP_ASYNC16(dst, src) \
    asm volatile("cp.async.cg.shared.global [%0], [%1], 16;" :: "r"(dst), "l"(src))
#define CP_COMMIT() asm volatile("cp.async.commit_group;" ::: "memory")
#define CP_WAIT1()  asm volatile("cp.async.wait_group 1;"  ::: "memory")
#define CP_WAIT0()  asm volatile("cp.async.wait_group 0;"  ::: "memory")

// ---------------- prep: transpose weights (Wq / GRU) ----------------
__global__ void prep_w(const float* __restrict__ Wq, const float* __restrict__ wih,
                       const float* __restrict__ whh) {
    int idx = blockIdx.x*256 + threadIdx.x;          // < 196608
    if (idx < 256*256) {
        int d = idx >> 8, o = idx & 255;
        g_WqT[idx] = Wq[o*256 + d];
    }
    {
        int d = idx / 768, o = idx - d*768;
        g_WihT[idx] = wih[o*256 + d];
        g_WhhT[idx] = whh[o*256 + d];
    }
}

// ---------------- prep: fp16 image of Wk|Wv (plain row-major) --------
__global__ void prep_b(const float* __restrict__ Wk, const float* __restrict__ Wv) {
    int o = blockIdx.x, k = threadIdx.x;
    float w = (o < 256) ? Wk[o*256 + k] : Wv[(o-256)*256 + k];
    g_B_img[o*256 + k] = __half_as_ushort(__float2half_rn(w));
}

// ---------------- HMMA K/V GEMM fragments (pure fp16) ----------
struct Frags {
    unsigned a0[4], a1[4];   // A (2 m-tiles)
    unsigned bh[8];          // B (2 n-sub-tiles)
};

__device__ __forceinline__ void load_frags(
    Frags& f, int ks, int half, unsigned buf,
    unsigned aBase0, unsigned aBase1, unsigned klA, unsigned xA,
    unsigned nB0row, unsigned nB1row, unsigned kbB, unsigned xB)
{
    unsigned kgA = (unsigned)(half*8 + ks)*2u + klA;
    unsigned aoff = ((kgA ^ xA) << 4);
    LDSM4(f.a0, aBase0 + aoff);
    LDSM4(f.a1, aBase1 + aoff);
    unsigned kgB = (unsigned)ks*2u + kbB;
    LDSM4(&f.bh[0], buf + nB0row + ((kgB ^ xB) << 4));
    LDSM4(&f.bh[4], buf + nB1row + ((kgB ^ xB) << 4));
}

__device__ __forceinline__ void do_mmas(float acc[2][4][4], const Frags& f) {
#pragma unroll
    for (int j = 0; j < 4; j++) {
        MMA16816(acc[0][j], f.a0, &f.bh[j*2]);
        MMA16816(acc[1][j], f.a1, &f.bh[j*2]);
    }
}

// ---------------- HMMA K/V GEMM: [262144,256] @ [256,512], fp16 ----
#define KV_SMEM 98304

__global__ void __launch_bounds__(256, 2)
kv_hmma(const float* __restrict__ x, const float* __restrict__ lw,
        const float* __restrict__ lb) {
    extern __shared__ char smem[];
    __shared__ float smu[128], srs[128];

    const unsigned sb  = smem_u32(smem);
    const unsigned sbB = sb + 65536u;
    int tid = threadIdx.x, wid = tid >> 5, lane = tid & 31;
    int m0 = blockIdx.x * 128;

    {
#pragma unroll
        for (int it = 0; it < 4; it++) {
            int u = tid + it*256;
            int o = u >> 4, g = u & 15;
            const char* src = (const char*)g_B_img + (size_t)o*512 + g*16;
            unsigned dst = sbB + o*256 + ((unsigned)(g ^ (o & 7)) << 4);
            CP_ASYNC16(dst, src);
        }
        CP_COMMIT();
    }

#pragma unroll 2
    for (int r = 0; r < 16; r++) {
        int row = wid*16 + r;
        const float4* xr = (const float4*)(x + (size_t)(m0 + row)*256);
        float4 v0 = xr[lane*2], v1 = xr[lane*2 + 1];
        float s  = v0.x + v0.y + v0.z + v0.w + v1.x + v1.y + v1.z + v1.w;
        float ss = v0.x*v0.x + v0.y*v0.y + v0.z*v0.z + v0.w*v0.w
                 + v1.x*v1.x + v1.y*v1.y + v1.z*v1.z + v1.w*v1.w;
#pragma unroll
        for (int o = 16; o; o >>= 1) {
            s  += __shfl_xor_sync(0xffffffffu, s,  o);
            ss += __shfl_xor_sync(0xffffffffu, ss, o);
        }
        if (lane == 0) {
            float mu = s * (1.f/256.f);
            smu[row] = mu;
            srs[row] = rsqrtf(ss * (1.f/256.f) - mu*mu + LN_EPS);
        }
    }
    __syncthreads();

    {
        int cpair = tid & 127;
        int c2 = cpair * 2;
        int rbase = (tid >> 7) * 64;
        float w0 = lw[c2], w1 = lw[c2+1], bb0 = lb[c2], bb1 = lb[c2+1];
        unsigned gA = (unsigned)(cpair >> 2);
        unsigned boff = (unsigned)(cpair & 3) * 4u;
#pragma unroll 4
        for (int r = 0; r < 64; r++) {
            int row = rbase + r;
            float2 xv = *(const float2*)&x[(size_t)(m0 + row)*256 + c2];
            float mu = smu[row], rs = srs[row];
            float v0 = (xv.x - mu)*rs*w0 + bb0;
            float v1 = (xv.y - mu)*rs*w1 + bb1;
            unsigned hp = (unsigned)__half_as_ushort(__float2half_rn(v0)) |
                          ((unsigned)__half_as_ushort(__float2half_rn(v1)) << 16);
            unsigned phys = (unsigned)row*512u + ((gA ^ (unsigned)(row & 7)) << 4) + boff;
            *(unsigned*)(smem + phys) = hp;
        }
    }

    int mw = wid >> 1, nw = wid & 1;
    int rA0 = mw*32 + (lane & 15);
    int rA1 = rA0 + 16;
    unsigned klA = (unsigned)(lane >> 4);
    unsigned xA = (unsigned)(rA0 & 7);
    unsigned aBase0 = sb + (unsigned)rA0*512u;
    unsigned aBase1 = sb + (unsigned)rA1*512u;

    int nB0 = nw*32 + (lane & 7) + ((lane >> 4) & 1)*8;
    int nB1 = nB0 + 16;
    unsigned nB0row = (unsigned)nB0*256u;
    unsigned nB1row = (unsigned)nB1*256u;
    unsigned kbB = (unsigned)((lane >> 3) & 1);
    unsigned xB = (unsigned)(nB0 & 7);

    float acc[2][4][4];
#pragma unroll
    for (int i = 0; i < 2; i++)
#pragma unroll
        for (int j = 0; j < 4; j++)
#pragma unroll
            for (int q = 0; q < 4; q++) acc[i][j][q] = 0.f;

    for (int c = 0; c < 16; c++) {
        if (c + 1 < 16) {
            int nbn = (c + 1) >> 1, halfn = (c + 1) & 1;
            unsigned bufn = sbB + (unsigned)((c + 1) & 1)*16384u;
#pragma unroll
            for (int it = 0; it < 4; it++) {
                int u = tid + it*256;
                int o = u >> 4, g = u & 15;
                const char* src = (const char*)g_B_img
                    + (size_t)(nbn*64 + o)*512 + halfn*256 + g*16;
                unsigned dst = bufn + o*256 + ((unsigned)(g ^ (o & 7)) << 4);
                CP_ASYNC16(dst, src);
            }
            CP_COMMIT();
            CP_WAIT1();
        } else {
            CP_WAIT0();
        }
        __syncthreads();

        unsigned buf = sbB + (unsigned)(c & 1)*16384u;
        int half = c & 1;

        Frags fr0, fr1;
        load_frags(fr0, 0, half, buf, aBase0, aBase1, klA, xA,
                   nB0row, nB1row, kbB, xB);
#pragma unroll
        for (int ks = 0; ks < 8; ks++) {
            Frags& cur = (ks & 1) ? fr1 : fr0;
            Frags& nxt = (ks & 1) ? fr0 : fr1;
            if (ks < 7)
                load_frags(nxt, ks + 1, half, buf, aBase0, aBase1, klA, xA,
                           nB0row, nB1row, kbB, xB);
            do_mmas(acc, cur);
        }

        if (c & 1) {
            int nbidx = c >> 1;
#pragma unroll
            for (int i = 0; i < 2; i++) {
#pragma unroll
                for (int j = 0; j < 4; j++) {
                    int row = m0 + mw*32 + i*16 + (lane >> 2);
                    int col = nbidx*64 + nw*32 + j*8 + (lane & 3)*2;
                    __half2 h0 = __floats2half2_rn(acc[i][j][0], acc[i][j][1]);
                    __half2 h1 = __floats2half2_rn(acc[i][j][2], acc[i][j][3]);
                    if (nbidx < 4) {
                        *(__half2*)&g_k16[(size_t)row*256 + col]       = h0;
                        *(__half2*)&g_k16[(size_t)(row + 8)*256 + col] = h1;
                    } else {
                        int vc = col - 256;
                        *(__half2*)&g_v16[(size_t)row*256 + vc]       = h0;
                        *(__half2*)&g_v16[(size_t)(row + 8)*256 + vc] = h1;
                    }
                    acc[i][j][0] = acc[i][j][1] = acc[i][j][2] = acc[i][j][3] = 0.f;
                }
            }
        }
        __syncthreads();
    }
}

// ---------------- slot LN + q projection (+ zero denom & upd) --------------
__global__ void __launch_bounds__(256)
slot_q(int it, const float* __restrict__ cond,
       const float* __restrict__ lw, const float* __restrict__ lb) {
    const float* src = (it == 0) ? cond : (it == 1 ? g_slotsA : g_slotsB);
    int b = blockIdx.x, t = threadIdx.x, wid = t >> 5, lane = t & 31;

    __shared__ float sn[8][256];
    __shared__ float wt[32][256];

    const float4* row = (const float4*)(src + (size_t)(b*8 + wid)*256);
    float4 v0 = row[lane], v1 = row[lane + 32];
    float s  = v0.x + v0.y + v0.z + v0.w + v1.x + v1.y + v1.z + v1.w;
    float ss = v0.x*v0.x + v0.y*v0.y + v0.z*v0.z + v0.w*v0.w
             + v1.x*v1.x + v1.y*v1.y + v1.z*v1.z + v1.w*v1.w;
#pragma unroll
    for (int o = 16; o; o >>= 1) {
        s  += __shfl_xor_sync(0xffffffffu, s,  o);
        ss += __shfl_xor_sync(0xffffffffu, ss, o);
    }
    float mu = s * (1.f/256.f);
    float rs = rsqrtf(ss * (1.f/256.f) - mu*mu + LN_EPS);
#pragma unroll
    for (int i = 0; i < 2; i++) {
        float4 xv = i ? v1 : v0;
        int c = (lane + 32*i) * 4;
        float4 w4 = *(const float4*)&lw[c];
        float4 b4 = *(const float4*)&lb[c];
        sn[wid][c+0] = (xv.x - mu)*rs*w4.x + b4.x;
        sn[wid][c+1] = (xv.y - mu)*rs*w4.y + b4.y;
        sn[wid][c+2] = (xv.z - mu)*rs*w4.z + b4.z;
        sn[wid][c+3] = (xv.w - mu)*rs*w4.w + b4.w;
    }
    if (t < 32) g_denom[b*32 + t] = 0.f;
#pragma unroll
    for (int i = 0; i < 8; i++) g_upd[b*2048 + i*256 + t] = 0.f;
    __syncthreads();

    float acc[8] = {0,0,0,0,0,0,0,0};
    for (int d0 = 0; d0 < 256; d0 += 32) {
        __syncthreads();
#pragma unroll
        for (int i = 0; i < 8; i++) {
            int u = t + i*256;
            int dd = u >> 6, g = u & 63;
            *(float4*)&wt[dd][g*4] = *(const float4*)&g_WqT[(d0 + dd)*256 + g*4];
        }
        __syncthreads();
#pragma unroll 4
        for (int dd = 0; dd < 32; dd++) {
            float w = wt[dd][t];
#pragma unroll
            for (int r = 0; r < 8; r++) acc[r] += sn[r][d0 + dd] * w;
        }
    }
#pragma unroll
    for (int r = 0; r < 8; r++) g_q[(size_t)(b*8 + r)*256 + t] = acc[r] * SCALE;
}

// ---------------- FUSED HMMA attention: dots + softmax + updates ----------
// grid (8, 64): CTA = (jt, b), 512 j per CTA, 8 warps.
// smem: Q'[32x256 fp16 swz] 16K | K/V stream 2x16K | attn[32x512 fp16 swz] 32K
#define AT_SMEM 81920

__global__ void __launch_bounds__(256, 2)
attn_hmma(float* __restrict__ out_stack, float* __restrict__ out_last) {
    extern __shared__ char smem[];
    const unsigned sb = smem_u32(smem);
    const unsigned sQ = sb;
    const unsigned sB = sb + 16384u;
    const unsigned sA = sb + 49152u;
    int tid = threadIdx.x, wid = tid >> 5, lane = tid & 31;
    int b = blockIdx.y, jt = blockIdx.x;
    size_t jrow = (size_t)b*NN + (size_t)jt*512;

    // prefetch chunk 0 (K: nc=0, kh=0)
    {
        const char* src0 = (const char*)(g_k16 + jrow*256);
#pragma unroll
        for (int it2 = 0; it2 < 4; it2++) {
            int u = tid + it2*256;
            int o = u >> 4, g = u & 15;
            unsigned dst = sB + o*256 + ((unsigned)(g ^ (o & 7)) << 4);
            CP_ASYNC16(dst, src0 + (size_t)o*512 + g*16);
        }
        CP_COMMIT();
    }

    // build Q' (block-diagonal zero-padded), fp16, kv-A swizzle
    {
        int cpair = tid & 127;
        int c2 = cpair * 2;
        int hcol = c2 >> 6;
        int rbase = (tid >> 7) * 16;
        unsigned gA = (unsigned)(cpair >> 2);
        unsigned boff = (unsigned)(cpair & 3) * 4u;
#pragma unroll
        for (int r = 0; r < 16; r++) {
            int row = rbase + r;               // ih = i*4 + h
            unsigned hp = 0u;
            if ((row & 3) == hcol) {
                float2 qv = *(const float2*)&g_q[(size_t)(b*8 + (row >> 2))*256 + c2];
                hp = (unsigned)__half_as_ushort(__float2half_rn(qv.x)) |
                     ((unsigned)__half_as_ushort(__float2half_rn(qv.y)) << 16);
            }
            unsigned phys = (unsigned)row*512u + ((gA ^ (unsigned)(row & 7)) << 4) + boff;
            *(unsigned*)(smem + phys) = hp;
        }
    }

    unsigned rA   = (unsigned)(lane & 15);
    unsigned klA  = (unsigned)(lane >> 4);
    unsigned xA   = rA & 7u;
    unsigned rB   = (unsigned)(wid*8 + (lane & 7));   // dots B row (j local in chunk)
    unsigned gBl  = (unsigned)(lane >> 3);            // 0..3
    unsigned rVl0 = (unsigned)(lane & 15);            // upd V row base
    unsigned dgl  = (unsigned)(wid*2 + (lane >> 4));  // upd V d-granule

    float acc[2][4];
#pragma unroll
    for (int i = 0; i < 2; i++) { acc[i][0]=acc[i][1]=acc[i][2]=acc[i][3]=0.f; }
    float dsum[4] = {0.f, 0.f, 0.f, 0.f};
    float accU[2][2][4];
#pragma unroll
    for (int i = 0; i < 2; i++)
#pragma unroll
        for (int n = 0; n < 2; n++)
            { accU[i][n][0]=accU[i][n][1]=accU[i][n][2]=accU[i][n][3]=0.f; }

    for (int c = 0; c < 32; c++) {
        if (c + 1 < 32) {
            int cn = c + 1;
            const char* srcb;
            if (cn < 16)
                srcb = (const char*)(g_k16 + (jrow + (size_t)(cn >> 1)*64)*256 + (cn & 1)*128);
            else {
                int cv = cn - 16;
                srcb = (const char*)(g_v16 + (jrow + (size_t)(cv & 7)*64)*256 + (cv >> 3)*128);
            }
            unsigned bufn = sB + (unsigned)(cn & 1)*16384u;
#pragma unroll
            for (int it2 = 0; it2 < 4; it2++) {
                int u = tid + it2*256;
                int o = u >> 4, g = u & 15;
                unsigned dst = bufn + o*256 + ((unsigned)(g ^ (o & 7)) << 4);
                CP_ASYNC16(dst, srcb + (size_t)o*512 + g*16);
            }
            CP_COMMIT();
            CP_WAIT1();
        } else {
            CP_WAIT0();
        }
        __syncthreads();

        unsigned buf = sB + (unsigned)(c & 1)*16384u;

        if (c < 16) {
            // ================= dots phase =================
            int kh = c & 1;
#pragma unroll
            for (int ks2 = 0; ks2 < 4; ks2++) {
                unsigned bb[4];
                unsigned gB = (unsigned)(ks2*4) + gBl;
                LDSM4(bb, buf + rB*256u + ((gB ^ (rB & 7u)) << 4));
#pragma unroll
                for (int hf = 0; hf < 2; hf++) {
                    int ks = ks2*2 + hf;
                    unsigned kg = (unsigned)(kh*16 + ks*2) + klA;
                    unsigned aoff = ((kg ^ xA) << 4);
                    unsigned a0[4], a1[4];
                    LDSM4(a0, sQ + rA*512u + aoff);
                    LDSM4(a1, sQ + (rA + 16u)*512u + aoff);
                    MMA16816(acc[0], a0, &bb[hf*2]);
                    MMA16816(acc[1], a1, &bb[hf*2]);
                }
            }
            if (kh == 1) {
                int nc = c >> 1;
                // softmax across 32 rows for this thread's 2 columns
                float m0 = fmaxf(fmaxf(acc[0][0], acc[0][2]), fmaxf(acc[1][0], acc[1][2]));
                float m1 = fmaxf(fmaxf(acc[0][1], acc[0][3]), fmaxf(acc[1][1], acc[1][3]));
#pragma unroll
                for (int o = 4; o <= 16; o <<= 1) {
                    m0 = fmaxf(m0, __shfl_xor_sync(0xffffffffu, m0, o));
                    m1 = fmaxf(m1, __shfl_xor_sync(0xffffffffu, m1, o));
                }
                float e[2][4];
                float s0 = 0.f, s1 = 0.f;
#pragma unroll
                for (int i = 0; i < 2; i++) {
                    e[i][0] = __expf(acc[i][0] - m0); s0 += e[i][0];
                    e[i][2] = __expf(acc[i][2] - m0); s0 += e[i][2];
                    e[i][1] = __expf(acc[i][1] - m1); s1 += e[i][1];
                    e[i][3] = __expf(acc[i][3] - m1); s1 += e[i][3];
                }
#pragma unroll
                for (int o = 4; o <= 16; o <<= 1) {
                    s0 += __shfl_xor_sync(0xffffffffu, s0, o);
                    s1 += __shfl_xor_sync(0xffffffffu, s1, o);
                }
                float i0 = 1.f / s0, i1 = 1.f / s1;
#pragma unroll
                for (int i = 0; i < 2; i++) {
                    e[i][0] *= i0; e[i][2] *= i0;
                    e[i][1] *= i1; e[i][3] *= i1;
                }
                dsum[0] += e[0][0] + e[0][1];
                dsum[1] += e[0][2] + e[0][3];
                dsum[2] += e[1][0] + e[1][1];
                dsum[3] += e[1][2] + e[1][3];

                // store attn fp16 to sA (row stride 1024B, XOR swizzle)
                int jl = nc*64 + wid*8 + (lane & 3)*2;
                unsigned gj = (unsigned)(jl >> 3);
                unsigned jb = (unsigned)(jl & 7)*2u;
#pragma unroll
                for (int i = 0; i < 2; i++) {
                    unsigned row0 = (unsigned)(i*16) + (unsigned)(lane >> 2);
                    unsigned row1 = row0 + 8u;
                    __half2 h0 = __floats2half2_rn(e[i][0], e[i][1]);
                    __half2 h1 = __floats2half2_rn(e[i][2], e[i][3]);
                    *(__half2*)(smem + 49152u + row0*1024u + ((gj ^ (row0 & 7u)) << 4) + jb) = h0;
                    *(__half2*)(smem + 49152u + row1*1024u + ((gj ^ (row1 & 7u)) << 4) + jb) = h1;
                }

                // head-mean outputs
                float hm0[4] = { e[0][0], e[0][2], e[1][0], e[1][2] };
                float hm1[4] = { e[0][1], e[0][3], e[1][1], e[1][3] };
#pragma unroll
                for (int idx = 0; idx < 4; idx++) {
                    hm0[idx] += __shfl_xor_sync(0xffffffffu, hm0[idx], 4);
                    hm0[idx] += __shfl_xor_sync(0xffffffffu, hm0[idx], 8);
                    hm1[idx] += __shfl_xor_sync(0xffffffffu, hm1[idx], 4);
                    hm1[idx] += __shfl_xor_sync(0xffffffffu, hm1[idx], 8);
                }
                if ((lane & 12) == 0) {
                    int ib = (lane >> 4) & 1;
                    int col = jt*512 + nc*64 + wid*8 + (lane & 3)*2;
#pragma unroll
                    for (int idx = 0; idx < 4; idx++) {
                        int iSlot = idx*2 + ib;
                        size_t o = (size_t)(b*8 + iSlot)*NN + col;
                        float2 mv; mv.x = hm0[idx]*0.25f; mv.y = hm1[idx]*0.25f;
                        *(float2*)&out_stack[o] = mv;
                        if (out_last) *(float2*)&out_last[o] = mv;
                    }
                }
#pragma unroll
                for (int i = 0; i < 2; i++)
                    { acc[i][0]=acc[i][1]=acc[i][2]=acc[i][3]=0.f; }

                if (c == 15) {
#pragma unroll
                    for (int idx = 0; idx < 4; idx++) {
                        float v = dsum[idx];
                        v += __shfl_xor_sync(0xffffffffu, v, 1);
                        v += __shfl_xor_sync(0xffffffffu, v, 2);
                        if ((lane & 3) == 0)
                            atomicAdd(&g_denom[b*32 + idx*8 + (lane >> 2)], v);
                    }
                }
            }
        } else {
            // ================= upd phase =================
            int cv = c - 16;
            int jc = cv & 7, dh = cv >> 3;
#pragma unroll
            for (int ks = 0; ks < 4; ks++) {
                unsigned kg = (unsigned)(jc*8 + ks*2) + klA;
                unsigned aoff = ((kg ^ xA) << 4);
                unsigned a0[4], a1[4];
                LDSM4(a0, sA + rA*1024u + aoff);
                LDSM4(a1, sA + (rA + 16u)*1024u + aoff);
                unsigned rV = (unsigned)(ks*16) + rVl0;
                unsigned bv[4];
                LDSM4T(bv, buf + rV*256u + ((dgl ^ (rV & 7u)) << 4));
                MMA16816(accU[0][0], a0, &bv[0]);
                MMA16816(accU[1][0], a1, &bv[0]);
                MMA16816(accU[0][1], a0, &bv[2]);
                MMA16816(accU[1][1], a1, &bv[2]);
            }
            if (jc == 7) {
                int head = dh*2 + (wid >> 2);
                if (((lane >> 2) & 3) == head) {
#pragma unroll
                    for (int i = 0; i < 2; i++)
#pragma unroll
                        for (int n = 0; n < 2; n++) {
                            int row0 = i*16 + (lane >> 2);
                            int row1 = row0 + 8;
                            int d = dh*128 + wid*16 + n*8 + (lane & 3)*2;
                            atomicAdd(&g_upd[(size_t)(b*8 + (row0 >> 2))*256 + d],     accU[i][n][0]);
                            atomicAdd(&g_upd[(size_t)(b*8 + (row0 >> 2))*256 + d + 1], accU[i][n][1]);
                            atomicAdd(&g_upd[(size_t)(b*8 + (row1 >> 2))*256 + d],     accU[i][n][2]);
                            atomicAdd(&g_upd[(size_t)(b*8 + (row1 >> 2))*256 + d + 1], accU[i][n][3]);
                        }
                }
#pragma unroll
                for (int i = 0; i < 2; i++)
#pragma unroll
                    for (int n = 0; n < 2; n++)
                        { accU[i][n][0]=accU[i][n][1]=accU[i][n][2]=accU[i][n][3]=0.f; }
            }
        }
        __syncthreads();
    }
}

// ---------------- GRU cell (normalizes updates by denom) -------------------
__global__ void __launch_bounds__(256)
gru_kernel(int it, const float* __restrict__ cond, float* __restrict__ out_slots,
           const float* __restrict__ bih, const float* __restrict__ bhh) {
    const float* hsrc = (it == 0) ? cond : (it == 1 ? g_slotsA : g_slotsB);
    float* dst = (it == 0) ? g_slotsA : (it == 1 ? g_slotsB : out_slots);
    int t = threadIdx.x;
    __shared__ float u_s[4][256], h_s[4][256];
#pragma unroll
    for (int r = 0; r < 4; r++) {
        int row = blockIdx.x*4 + r;
        int bb = row >> 3, ii = row & 7;
        float dinv = 1.f / (g_denom[bb*32 + ii*4 + (t >> 6)] + SUM_EPS);
        u_s[r][t] = g_upd[row*256 + t] * dinv;
        h_s[r][t] = hsrc[row*256 + t];
    }
    __syncthreads();
    float axr[4] = {0,0,0,0}, axz[4] = {0,0,0,0}, axn[4] = {0,0,0,0};
    float ahr[4] = {0,0,0,0}, ahz[4] = {0,0,0,0}, ahn[4] = {0,0,0,0};
#pragma unroll 2
    for (int dd = 0; dd < 256; dd++) {
        float wr = g_WihT[dd*768 + t],       wz = g_WihT[dd*768 + 256 + t];
        float wn = g_WihT[dd*768 + 512 + t];
        float vr = g_WhhT[dd*768 + t],       vz = g_WhhT[dd*768 + 256 + t];
        float vn = g_WhhT[dd*768 + 512 + t];
#pragma unroll
        for (int r = 0; r < 4; r++) {
            float u = u_s[r][dd], hh = h_s[r][dd];
            axr[r] += u*wr;  axz[r] += u*wz;  axn[r] += u*wn;
            ahr[r] += hh*vr; ahz[r] += hh*vz; ahn[r] += hh*vn;
        }
    }
    float br = bih[t], bz = bih[256 + t], bn = bih[512 + t];
    float cr = bhh[t], cz = bhh[256 + t], cn = bhh[512 + t];
#pragma unroll
    for (int r = 0; r < 4; r++) {
        float rg = 1.f / (1.f + __expf(-(axr[r] + ahr[r] + br + cr)));
        float zg = 1.f / (1.f + __expf(-(axz[r] + ahz[r] + bz + cz)));
        float ng = tanhf(axn[r] + bn + rg*(ahn[r] + cn));
        int row = blockIdx.x*4 + r;
        dst[row*256 + t] = (1.f - zg)*ng + zg*h_s[r][t];
    }
}

// ---------------- launch ----------------
extern "C" void kernel_launch(void* const* d_in, const int* in_sizes, int n_in,
                              void* d_out, int out_size) {
    (void)in_sizes; (void)n_in; (void)out_size;
    const float* x    = (const float*)d_in[0];
    const float* cond = (const float*)d_in[1];
    const float* lniw = (const float*)d_in[2];
    const float* lnib = (const float*)d_in[3];
    const float* lnsw = (const float*)d_in[4];
    const float* lnsb = (const float*)d_in[5];
    const float* Wq   = (const float*)d_in[6];
    const float* Wk   = (const float*)d_in[7];
    const float* Wv   = (const float*)d_in[8];
    const float* wih  = (const float*)d_in[9];
    const float* whh  = (const float*)d_in[10];
    const float* bih  = (const float*)d_in[11];
    const float* bhh  = (const float*)d_in[12];

    float* out       = (float*)d_out;
    float* out_slots = out;                       // [64,8,256]
    float* out_last  = out + 131072;              // [64,8,4096]
    float* out_stack = out + 131072 + 2097152;    // [3,64,8,4096]

    cudaFuncSetAttribute(kv_hmma, cudaFuncAttributeMaxDynamicSharedMemorySize, KV_SMEM);
    cudaFuncSetAttribute(attn_hmma, cudaFuncAttributeMaxDynamicSharedMemorySize, AT_SMEM);

    prep_w<<<768, 256>>>(Wq, wih, whh);
    prep_b<<<512, 256>>>(Wk, Wv);
    kv_hmma<<<2048, 256, KV_SMEM>>>(x, lniw, lnib);

    for (int it = 0; it < 3; it++) {
        slot_q<<<64, 256>>>(it, cond, lnsw, lnsb);
        attn_hmma<<<dim3(8, 64), 256, AT_SMEM>>>(out_stack + (size_t)it*2097152,
                                                 (it == 2) ? out_last : (float*)0);
        gru_kernel<<<128, 256>>>(it, cond, out_slots, bih, bhh);
    }
}